// round 2
// baseline (speedup 1.0000x reference)
#include <cuda_runtime.h>
#include <math.h>

// ---------------------------------------------------------------------------
// Model constants
// ---------------------------------------------------------------------------
#define Tn  128
#define Dn  1024
#define Ln  8
#define Hn  16
#define Fn  2816
#define DHn 64
#define Vn  32000

// ---------------------------------------------------------------------------
// Scratch (device globals: allocation-free per harness rules)
// ---------------------------------------------------------------------------
__device__ float g_X [Tn * Dn];        // residual stream
__device__ float g_XN[Tn * Dn];        // rmsnorm output
__device__ float g_Q [Tn * Dn];
__device__ float g_Kc[Tn * Dn];
__device__ float g_Vc[Tn * Dn];
__device__ float g_A [Tn * Dn];        // attention output (pre-Wo)
__device__ float g_H [Tn * Fn];        // silu(gate)*up
__device__ float g_part[4 * Tn * Fn];  // split-K / gate-up partials (5.77 MB)
__device__ float g_xl[Dn];             // final normed hidden (last token)

// ---------------------------------------------------------------------------
// Helpers
// ---------------------------------------------------------------------------
__device__ __forceinline__ float blockReduceSum(float v) {
    __shared__ float red[32];
    __shared__ float tot;
    int lane = threadIdx.x & 31, warp = threadIdx.x >> 5;
#pragma unroll
    for (int o = 16; o > 0; o >>= 1) v += __shfl_xor_sync(0xffffffffu, v, o);
    if (lane == 0) red[warp] = v;
    __syncthreads();
    int nw = (blockDim.x + 31) >> 5;
    if (warp == 0) {
        float x = (threadIdx.x < nw) ? red[threadIdx.x] : 0.f;
#pragma unroll
        for (int o = 16; o > 0; o >>= 1) x += __shfl_xor_sync(0xffffffffu, x, o);
        if (threadIdx.x == 0) tot = x;
    }
    __syncthreads();
    return tot;
}

// ---------------------------------------------------------------------------
// Embedding gather: g_X[t,:] = emb[ids[t],:]
// ---------------------------------------------------------------------------
__global__ void k_embed(const int* __restrict__ ids, const float* __restrict__ emb) {
    int t = blockIdx.x;
    int row = ids[t];
    const float4* src = (const float4*)(emb + (size_t)row * Dn);
    float4* dst = (float4*)(g_X + (size_t)t * Dn);
    for (int i = threadIdx.x; i < Dn / 4; i += blockDim.x) dst[i] = src[i];
}

// ---------------------------------------------------------------------------
// RMSNorm: g_XN[t,:] = g_X[t,:] * rsqrt(mean(x^2)+eps) * w
// grid = Tn, block = 256
// ---------------------------------------------------------------------------
__global__ void k_rmsnorm(const float* __restrict__ w) {
    int t = blockIdx.x;
    const float4* x4 = (const float4*)(g_X + (size_t)t * Dn);
    const float4* w4 = (const float4*)w;
    float4* o4 = (float4*)(g_XN + (size_t)t * Dn);
    float4 xv = x4[threadIdx.x];                    // 256 threads * 4 = 1024
    float ss = xv.x * xv.x + xv.y * xv.y + xv.z * xv.z + xv.w * xv.w;
    ss = blockReduceSum(ss);
    float inv = rsqrtf(ss / (float)Dn + 1e-5f);
    float4 wv = w4[threadIdx.x];
    float4 r = make_float4(xv.x * inv * wv.x, xv.y * inv * wv.y,
                           xv.z * inv * wv.z, xv.w * inv * wv.w);
    o4[threadIdx.x] = r;
}

// Final rmsnorm of last token into g_xl
__global__ void k_finalnorm(const float* __restrict__ w) {
    const float4* x4 = (const float4*)(g_X + (size_t)(Tn - 1) * Dn);
    const float4* w4 = (const float4*)w;
    float4* o4 = (float4*)g_xl;
    float4 xv = x4[threadIdx.x];
    float ss = xv.x * xv.x + xv.y * xv.y + xv.z * xv.z + xv.w * xv.w;
    ss = blockReduceSum(ss);
    float inv = rsqrtf(ss / (float)Dn + 1e-5f);
    float4 wv = w4[threadIdx.x];
    o4[threadIdx.x] = make_float4(xv.x * inv * wv.x, xv.y * inv * wv.y,
                                  xv.z * inv * wv.z, xv.w * inv * wv.w);
}

// ---------------------------------------------------------------------------
// SGEMM core: 64x64 block tile, BK=16, 256 threads, 4x4 per-thread microtile,
// single-stage smem with register prefetch of next tile.
// A: row-major [.., lda], B: row-major [.., ldb], C: row-major [.., ldc]
// All dims here divide evenly (M=128, N in {1024,2816}, kc multiple of 16).
// ---------------------------------------------------------------------------
__device__ __forceinline__ void gemm_block(
    const float* __restrict__ A, int lda,
    const float* __restrict__ B, int ldb,
    float* __restrict__ C, int ldc, int kc)
{
    __shared__ float As[16][64];
    __shared__ float Bs[16][64];
    const int m0 = blockIdx.y * 64, n0 = blockIdx.x * 64;
    const int tid = threadIdx.x;
    const int ar = tid >> 2, ac = (tid & 3) << 2;   // A tile: 64 rows x 16 cols
    const int br = tid >> 4, bc = (tid & 15) << 2;  // B tile: 16 rows x 64 cols
    const int ty = tid >> 4, tx = tid & 15;

    float4 aReg = *(const float4*)(A + (size_t)(m0 + ar) * lda + ac);
    float4 bReg = *(const float4*)(B + (size_t)br * ldb + n0 + bc);

    float acc[4][4] = {};

    for (int kk = 0; kk < kc; kk += 16) {
        As[ac + 0][ar] = aReg.x; As[ac + 1][ar] = aReg.y;
        As[ac + 2][ar] = aReg.z; As[ac + 3][ar] = aReg.w;
        *(float4*)&Bs[br][bc] = bReg;
        __syncthreads();
        if (kk + 16 < kc) {
            aReg = *(const float4*)(A + (size_t)(m0 + ar) * lda + (kk + 16) + ac);
            bReg = *(const float4*)(B + (size_t)(kk + 16 + br) * ldb + n0 + bc);
        }
#pragma unroll
        for (int k = 0; k < 16; k++) {
            float a[4], b[4];
#pragma unroll
            for (int j = 0; j < 4; j++) a[j] = As[k][(ty << 2) + j];
#pragma unroll
            for (int j = 0; j < 4; j++) b[j] = Bs[k][(tx << 2) + j];
#pragma unroll
            for (int ii = 0; ii < 4; ii++)
#pragma unroll
                for (int jj = 0; jj < 4; jj++)
                    acc[ii][jj] = fmaf(a[ii], b[jj], acc[ii][jj]);
        }
        __syncthreads();
    }
#pragma unroll
    for (int ii = 0; ii < 4; ii++) {
        float4 v = make_float4(acc[ii][0], acc[ii][1], acc[ii][2], acc[ii][3]);
        *(float4*)(C + (size_t)(m0 + (ty << 2) + ii) * ldc + n0 + (tx << 2)) = v;
    }
}

// QKV: grid (16, 2, 3), A = g_XN [128,1024]
__global__ void k_qkv(const float* __restrict__ Wq, const float* __restrict__ Wk,
                      const float* __restrict__ Wv) {
    const float* B = (blockIdx.z == 0) ? Wq : (blockIdx.z == 1) ? Wk : Wv;
    float* C = (blockIdx.z == 0) ? g_Q : (blockIdx.z == 1) ? g_Kc : g_Vc;
    gemm_block(g_XN, Dn, B, Dn, C, Dn, Dn);
}

// Split-K=4 GEMM into g_part. aSel: 0 -> A=g_A (K=1024), 1 -> A=g_H (K=2816)
__global__ void k_gemm_split4(int aSel, const float* __restrict__ B, int N, int K) {
    const float* A = aSel ? g_H : g_A;
    int lda = aSel ? Fn : Dn;
    int kc = K >> 2;
    int k0 = blockIdx.z * kc;
    gemm_block(A + k0, lda, B + (size_t)k0 * N, N,
               g_part + (size_t)blockIdx.z * Tn * N, N, kc);
}

// Gate/Up fused, split-K=2 each. z = mat*2 + split. grid (44, 2, 4)
__global__ void k_gateup(const float* __restrict__ Wg, const float* __restrict__ Wu) {
    int mat = blockIdx.z >> 1, sp = blockIdx.z & 1;
    const float* Bp = mat ? Wu : Wg;
    int kc = Dn >> 1;
    int k0 = sp * kc;
    gemm_block(g_XN + k0, Dn, Bp + (size_t)k0 * Fn, Fn,
               g_part + (size_t)blockIdx.z * Tn * Fn, Fn, kc);
}

// Residual add with split-K reduce: g_X += sum_z g_part[z]
__global__ void k_reduceX() {
    int i = blockIdx.x * blockDim.x + threadIdx.x;
    g_X[i] += g_part[i] + g_part[Tn * Dn + i]
            + g_part[2 * Tn * Dn + i] + g_part[3 * Tn * Dn + i];
}

// SiLU(gate)*up with gate/up split-K reduce fused
__global__ void k_silu() {
    int i = blockIdx.x * blockDim.x + threadIdx.x;
    float g = g_part[i] + g_part[Tn * Fn + i];
    float u = g_part[2 * Tn * Fn + i] + g_part[3 * Tn * Fn + i];
    float s = g / (1.f + expf(-g));
    g_H[i] = s * u;
}

// ---------------------------------------------------------------------------
// RoPE on Q and K. grid = Tn, block = 512 (16 heads x 32 rotation pairs)
// out[d]    = x[d]*cos - x[d+32]*sin
// out[d+32] = x[d+32]*cos + x[d]*sin,  angle = t * base^(-d/32)
// ---------------------------------------------------------------------------
__global__ void k_rope() {
    int t = blockIdx.x;
    int h = threadIdx.x >> 5;
    int d = threadIdx.x & 31;
    double inv = pow(10000.0, -(double)d / 32.0);
    double ang = (double)t * inv;
    float c = (float)cos(ang), s = (float)sin(ang);
    int i0 = t * Dn + h * DHn + d, i1 = i0 + 32;
    float q0 = g_Q[i0], q1 = g_Q[i1];
    g_Q[i0] = q0 * c - q1 * s;
    g_Q[i1] = q1 * c + q0 * s;
    float k0 = g_Kc[i0], k1 = g_Kc[i1];
    g_Kc[i0] = k0 * c - k1 * s;
    g_Kc[i1] = k1 * c + k0 * s;
}

// ---------------------------------------------------------------------------
// Causal attention, exact softmax. grid (Tn, Hn), block 128.
// K (then V) staged in padded smem; matches reference -1e9 masking.
// ---------------------------------------------------------------------------
__global__ void k_attn() {
    int i = blockIdx.x, h = blockIdx.y;
    int tid = threadIdx.x;
    __shared__ float q[DHn];
    __shared__ float KV[Tn][DHn + 1];
    __shared__ float p[Tn];
    __shared__ float rmax[4], rsum[4];

    if (tid < DHn) q[tid] = g_Q[(size_t)i * Dn + h * DHn + tid];
    for (int idx = tid; idx < Tn * DHn; idx += 128) {
        int r = idx >> 6, c = idx & 63;
        KV[r][c] = g_Kc[(size_t)r * Dn + h * DHn + c];
    }
    __syncthreads();

    float sc;
    if (tid <= i) {
        float s = 0.f;
#pragma unroll
        for (int d = 0; d < DHn; d++) s = fmaf(q[d], KV[tid][d], s);
        sc = s * 0.125f;                     // 1/sqrt(64)
    } else {
        sc = -1e9f;
    }

    float m = sc;
#pragma unroll
    for (int o = 16; o > 0; o >>= 1) m = fmaxf(m, __shfl_xor_sync(0xffffffffu, m, o));
    if ((tid & 31) == 0) rmax[tid >> 5] = m;
    __syncthreads();
    m = fmaxf(fmaxf(rmax[0], rmax[1]), fmaxf(rmax[2], rmax[3]));

    float e = expf(sc - m);
    float s = e;
#pragma unroll
    for (int o = 16; o > 0; o >>= 1) s += __shfl_xor_sync(0xffffffffu, s, o);
    if ((tid & 31) == 0) rsum[tid >> 5] = s;
    __syncthreads();
    s = rsum[0] + rsum[1] + rsum[2] + rsum[3];
    p[tid] = e / s;
    __syncthreads();

    // stage V over K
    for (int idx = tid; idx < Tn * DHn; idx += 128) {
        int r = idx >> 6, c = idx & 63;
        KV[r][c] = g_Vc[(size_t)r * Dn + h * DHn + c];
    }
    __syncthreads();

    if (tid < DHn) {
        float o = 0.f;
#pragma unroll 8
        for (int j = 0; j < Tn; j++) o = fmaf(p[j], KV[j][tid], o);
        g_A[(size_t)i * Dn + h * DHn + tid] = o;
    }
}

// ---------------------------------------------------------------------------
// Tied lm_head GEMV: logits[v] = dot(emb[v,:], g_xl). One warp per row.
// grid = Vn/8, block = 256 (8 warps)
// ---------------------------------------------------------------------------
__global__ void k_logits(const float* __restrict__ emb, float* __restrict__ out) {
    __shared__ float4 xs[Dn / 4];
    for (int i = threadIdx.x; i < Dn / 4; i += blockDim.x)
        xs[i] = ((const float4*)g_xl)[i];
    __syncthreads();
    int warp = threadIdx.x >> 5, lane = threadIdx.x & 31;
    int row = blockIdx.x * 8 + warp;
    if (row < Vn) {
        const float4* e4 = (const float4*)(emb + (size_t)row * Dn);
        float s = 0.f;
#pragma unroll
        for (int k = lane; k < Dn / 4; k += 32) {
            float4 a = e4[k], b = xs[k];
            s += a.x * b.x + a.y * b.y + a.z * b.z + a.w * b.w;
        }
#pragma unroll
        for (int o = 16; o > 0; o >>= 1) s += __shfl_xor_sync(0xffffffffu, s, o);
        if (lane == 0) out[row] = s;
    }
}

// ---------------------------------------------------------------------------
// Host orchestration (graph-capturable: kernel launches only)
// ---------------------------------------------------------------------------
extern "C" void kernel_launch(void* const* d_in, const int* in_sizes, int n_in,
                              void* d_out, int out_size) {
    const int*   ids       = (const int*)  d_in[0];
    const float* emb       = (const float*)d_in[1];
    const float* Wq        = (const float*)d_in[2];
    const float* Wk        = (const float*)d_in[3];
    const float* Wv        = (const float*)d_in[4];
    const float* Wo        = (const float*)d_in[5];
    const float* Wg        = (const float*)d_in[6];
    const float* Wu        = (const float*)d_in[7];
    const float* Wd        = (const float*)d_in[8];
    const float* attn_norm = (const float*)d_in[9];
    const float* ffn_norm  = (const float*)d_in[10];
    const float* norm_out  = (const float*)d_in[11];
    float* out = (float*)d_out;

    k_embed<<<Tn, 256>>>(ids, emb);

    for (int l = 0; l < Ln; l++) {
        const float* wq = Wq + (size_t)l * Dn * Dn;
        const float* wk = Wk + (size_t)l * Dn * Dn;
        const float* wv = Wv + (size_t)l * Dn * Dn;
        const float* wo = Wo + (size_t)l * Dn * Dn;
        const float* wg = Wg + (size_t)l * Dn * Fn;
        const float* wu = Wu + (size_t)l * Dn * Fn;
        const float* wd = Wd + (size_t)l * Fn * Dn;

        k_rmsnorm<<<Tn, 256>>>(attn_norm + (size_t)l * Dn);
        k_qkv<<<dim3(Dn / 64, Tn / 64, 3), 256>>>(wq, wk, wv);
        k_rope<<<Tn, 512>>>();
        k_attn<<<dim3(Tn, Hn), 128>>>();
        k_gemm_split4<<<dim3(Dn / 64, Tn / 64, 4), 256>>>(0, wo, Dn, Dn);
        k_reduceX<<<(Tn * Dn) / 256, 256>>>();

        k_rmsnorm<<<Tn, 256>>>(ffn_norm + (size_t)l * Dn);
        k_gateup<<<dim3(Fn / 64, Tn / 64, 4), 256>>>(wg, wu);
        k_silu<<<(Tn * Fn) / 256, 256>>>();
        k_gemm_split4<<<dim3(Dn / 64, Tn / 64, 4), 256>>>(1, wd, Dn, Fn);
        k_reduceX<<<(Tn * Dn) / 256, 256>>>();
    }

    k_finalnorm<<<1, 256>>>(norm_out);
    k_logits<<<(Vn + 7) / 8, 256>>>(emb, out);
}